// round 8
// baseline (speedup 1.0000x reference)
#include <cuda_runtime.h>
#include <cuda_fp16.h>
#include <math.h>

// Problem constants
#define B   64
#define T   100
#define S   1024
#define IN  256
#define TRG 512
#define ENC 512
#define G4  2048   // 4*TRG
#define NBLK 444   // persistent grid size

// Output layout offsets (floats)
#define OUT_OFF   0
#define HT_OFF    3276800
#define CT_OFF    3309568
#define HAT_OFF   3342336
#define ATTN_OFF  3375104
#define PAT_OFF   9928704
#define PGEN_OFF  9994240
#define PDH_OFF   10000640
#define LOSS_OFF  10033408

// ---------------- device state ----------------
__device__ __align__(16) __half  g_encproj_h[(size_t)B * S * TRG];   // 67 MB
__device__ __align__(16) __half  g_enc_h[(size_t)B * S * ENC];       // 67 MB
__device__ __align__(16) __half  g_wen_h[512 * 512];
__device__ __align__(16) __half  g_input_h[B * T * IN];
__device__ __align__(16) __half  g_wihx_h[G4 * IN];
__device__ __align__(16) __half  g_wr_h[(size_t)G4 * 1024];
__device__ __align__(16) __half  g_wde_h[TRG * TRG];
__device__ __align__(16) __half  g_x_h[B * 1024];                    // [ha | h] fp16
__device__ __align__(16) float   g_xg[(size_t)B * T * G4];
__device__ __align__(16) float g_h[B * TRG];
__device__ __align__(16) float g_c[2][B * TRG];                      // DOUBLE-BUFFERED (race fix)
__device__ __align__(16) float g_ha[B * TRG];
__device__ __align__(16) float g_pa[B * S];
__device__ __align__(16) float g_gp4[4][B * G4];
__device__ __align__(16) float g_hde4[4][B * TRG];
__device__ __align__(16) float g_attn[B * S];
__device__ __align__(16) float g_cenc4[4][B * TRG];

// grid barrier state
__device__ unsigned g_barA = 0;
__device__ volatile unsigned g_barG = 0;

__device__ __forceinline__ float warp_red_sum(float v) {
#pragma unroll
    for (int o = 16; o; o >>= 1) v += __shfl_xor_sync(0xffffffffu, v, o);
    return v;
}
__device__ __forceinline__ float sigmoidf_(float x) { return 1.0f / (1.0f + expf(-x)); }
__device__ __forceinline__ float tanh_ap(float x) {
    float y; asm("tanh.approx.f32 %0, %1;" : "=f"(y) : "f"(x)); return y;
}
__device__ __forceinline__ unsigned smem_u32(const void* p) {
    return (unsigned)__cvta_generic_to_shared(p);
}

__device__ __forceinline__ void gridbar() {
    __syncthreads();
    if (threadIdx.x == 0) {
        __threadfence();
        unsigned gen = g_barG;
        if (atomicAdd(&g_barA, 1u) == NBLK - 1) {
            g_barA = 0;
            __threadfence();
            g_barG = gen + 1;
        } else {
            while (g_barG == gen) { __nanosleep(64); }
        }
        __threadfence();
    }
    __syncthreads();
}

// ---------------- init ----------------
__global__ void k_init(const float* __restrict__ h0, const float* __restrict__ c0,
                       const float* __restrict__ h_attn, const float* __restrict__ past_attn) {
    int i = blockIdx.x * blockDim.x + threadIdx.x;
    if (i < B * TRG) {
        g_h[i] = h0[i]; g_c[0][i] = c0[i]; g_ha[i] = h_attn[i];
        int b = i >> 9, j = i & 511;
        g_x_h[b * 1024 + j]       = __float2half_rn(h_attn[i]);
        g_x_h[b * 1024 + 512 + j] = __float2half_rn(h0[i]);
    }
    if (i < B * S) g_pa[i] = past_attn[i];
}

__global__ void k_f2h(const float* __restrict__ src, __half* __restrict__ dst) {
    size_t i = ((size_t)blockIdx.x * blockDim.x + threadIdx.x) * 4;
    float4 v = *(const float4*)&src[i];
    __half2* d = (__half2*)&dst[i];
    d[0] = __floats2half2_rn(v.x, v.y);
    d[1] = __floats2half2_rn(v.z, v.w);
}

__global__ void k_wihx(const float* __restrict__ w_ih) {
    int n = blockIdx.x;
    for (int c = threadIdx.x; c < IN; c += 64)
        g_wihx_h[n * IN + c] = __float2half_rn(w_ih[(size_t)n * (IN + TRG) + c]);
}

__global__ void k_wr(const float* __restrict__ w_ih, const float* __restrict__ w_hh) {
    int n = blockIdx.x;
    for (int k = threadIdx.x; k < 1024; k += 256) {
        float v = (k < TRG) ? w_ih[(size_t)n * (IN + TRG) + IN + k]
                            : w_hh[(size_t)n * TRG + k - TRG];
        g_wr_h[(size_t)n * 1024 + k] = __float2half_rn(v);
    }
}

// ---------------- setup fp16 TC GEMM (encproj, xg) ----------------
template<bool OUT16>
__global__ void k_mma(const __half* __restrict__ A, const __half* __restrict__ W,
                      const float* __restrict__ bias, void* __restrict__ Cout,
                      int K, int ldc) {
    __shared__ __align__(16) char smem_raw[128 * 68 * 4];
    __shared__ float sBias[64];
    __half (*sA)[72] = (__half(*)[72])smem_raw;
    __half (*sB)[72] = (__half(*)[72])(smem_raw + 18432);

    const int m0 = blockIdx.y * 128;
    const int n0 = blockIdx.x * 64;
    const int tid = threadIdx.x;
    const int lane = tid & 31;
    const int w = tid >> 5;
    const int wm = (w >> 1) * 32;
    const int wn = (w & 1) * 32;

    if (OUT16 && tid < 64) sBias[tid] = bias[n0 + tid];

    float c[2][4][4];
#pragma unroll
    for (int i = 0; i < 2; i++)
#pragma unroll
        for (int j = 0; j < 4; j++)
#pragma unroll
            for (int q = 0; q < 4; q++) c[i][j][q] = 0.f;

    const int lrow = lane & 15;
    const int lcol = (lane >> 4) * 8;

    for (int k0 = 0; k0 < K; k0 += 64) {
        __syncthreads();
        {
            int r = tid >> 3, cc = (tid & 7) * 8;
#pragma unroll
            for (int p = 0; p < 4; p++)
                *(float4*)&sA[r + p * 32][cc] =
                    *(const float4*)&A[(size_t)(m0 + r + p * 32) * K + k0 + cc];
#pragma unroll
            for (int p = 0; p < 2; p++)
                *(float4*)&sB[r + p * 32][cc] =
                    *(const float4*)&W[(size_t)(n0 + r + p * 32) * K + k0 + cc];
        }
        __syncthreads();
#pragma unroll
        for (int kk = 0; kk < 4; kk++) {
            unsigned a[2][4], bf[4][2];
#pragma unroll
            for (int mt = 0; mt < 2; mt++) {
                unsigned addr = smem_u32(&sA[wm + mt * 16 + lrow][kk * 16 + lcol]);
                asm volatile("ldmatrix.sync.aligned.m8n8.x4.shared.b16 {%0,%1,%2,%3}, [%4];"
                             : "=r"(a[mt][0]), "=r"(a[mt][1]), "=r"(a[mt][2]), "=r"(a[mt][3])
                             : "r"(addr));
            }
#pragma unroll
            for (int bp = 0; bp < 2; bp++) {
                unsigned r0, r1, r2, r3;
                unsigned addr = smem_u32(&sB[wn + bp * 16 + lrow][kk * 16 + lcol]);
                asm volatile("ldmatrix.sync.aligned.m8n8.x4.shared.b16 {%0,%1,%2,%3}, [%4];"
                             : "=r"(r0), "=r"(r1), "=r"(r2), "=r"(r3) : "r"(addr));
                bf[bp * 2 + 0][0] = r0; bf[bp * 2 + 0][1] = r2;
                bf[bp * 2 + 1][0] = r1; bf[bp * 2 + 1][1] = r3;
            }
#pragma unroll
            for (int mt = 0; mt < 2; mt++)
#pragma unroll
                for (int nf = 0; nf < 4; nf++) {
                    asm volatile(
                        "mma.sync.aligned.m16n8k16.row.col.f32.f16.f16.f32 "
                        "{%0,%1,%2,%3}, {%4,%5,%6,%7}, {%8,%9}, {%0,%1,%2,%3};"
                        : "+f"(c[mt][nf][0]), "+f"(c[mt][nf][1]),
                          "+f"(c[mt][nf][2]), "+f"(c[mt][nf][3])
                        : "r"(a[mt][0]), "r"(a[mt][1]), "r"(a[mt][2]), "r"(a[mt][3]),
                          "r"(bf[nf][0]), "r"(bf[nf][1]));
                }
        }
    }
    __syncthreads();
    float (*sO)[68] = (float(*)[68])smem_raw;
    {
        int g = lane >> 2, tq = lane & 3;
#pragma unroll
        for (int mt = 0; mt < 2; mt++)
#pragma unroll
            for (int nf = 0; nf < 4; nf++) {
                int r = wm + mt * 16 + g;
                int cc = wn + (nf >> 1) * 16 + (nf & 1) * 8 + tq * 2;
                sO[r][cc]     = c[mt][nf][0]; sO[r][cc + 1]     = c[mt][nf][1];
                sO[r + 8][cc] = c[mt][nf][2]; sO[r + 8][cc + 1] = c[mt][nf][3];
            }
    }
    __syncthreads();
#pragma unroll
    for (int p = 0; p < 4; p++) {
        int idx = p * 256 + tid;
        int r = idx >> 3, c8 = (idx & 7) * 8;
        if (OUT16) {
            __half* C = (__half*)Cout;
            __half2 h[4];
#pragma unroll
            for (int q = 0; q < 4; q++)
                h[q] = __floats2half2_rn(sO[r][c8 + 2 * q] + sBias[c8 + 2 * q],
                                         sO[r][c8 + 2 * q + 1] + sBias[c8 + 2 * q + 1]);
            *(float4*)&C[(size_t)(m0 + r) * ldc + n0 + c8] = *(float4*)h;
        } else {
            float* C = (float*)Cout;
            *(float4*)&C[(size_t)(m0 + r) * ldc + n0 + c8]     = *(float4*)&sO[r][c8];
            *(float4*)&C[(size_t)(m0 + r) * ldc + n0 + c8 + 4] = *(float4*)&sO[r][c8 + 4];
        }
    }
}

// ---------------- persistent step-loop kernel ----------------
struct __align__(16) GemmS { __half A[64][72]; __half Bm[64][72]; };
struct __align__(16) HdeS  { __half A2[2][64][72]; __half Bm[64][72]; };
struct __align__(16) AttS  { float hde[TRG]; float cv[TRG]; float ww[TRG]; };
struct __align__(16) SmS   { float red[32]; float satt[256]; };
struct __align__(16) HaS   { float X[8][1024]; };
union __align__(16) SmemU {
    GemmS gemm; HdeS hde; AttS att; SmS sm; HaS ha;
};

__device__ __forceinline__ void mma_slab(const __half (*sA)[72], const __half (*sB)[72],
                                         int wm, int wn, int lane, float c[2][2][4]) {
    const int lrow = lane & 15;
    const int lcol = (lane >> 4) * 8;
#pragma unroll
    for (int kk = 0; kk < 4; kk++) {
        unsigned a[2][4], bf[2][2];
#pragma unroll
        for (int mt = 0; mt < 2; mt++) {
            unsigned addr = smem_u32(&sA[wm + mt * 16 + lrow][kk * 16 + lcol]);
            asm volatile("ldmatrix.sync.aligned.m8n8.x4.shared.b16 {%0,%1,%2,%3}, [%4];"
                         : "=r"(a[mt][0]), "=r"(a[mt][1]), "=r"(a[mt][2]), "=r"(a[mt][3])
                         : "r"(addr));
        }
        {
            unsigned r0, r1, r2, r3;
            unsigned addr = smem_u32(&sB[wn + lrow][kk * 16 + lcol]);
            asm volatile("ldmatrix.sync.aligned.m8n8.x4.shared.b16 {%0,%1,%2,%3}, [%4];"
                         : "=r"(r0), "=r"(r1), "=r"(r2), "=r"(r3) : "r"(addr));
            bf[0][0] = r0; bf[0][1] = r2;
            bf[1][0] = r1; bf[1][1] = r3;
        }
#pragma unroll
        for (int mt = 0; mt < 2; mt++)
#pragma unroll
            for (int nf = 0; nf < 2; nf++) {
                asm volatile(
                    "mma.sync.aligned.m16n8k16.row.col.f32.f16.f16.f32 "
                    "{%0,%1,%2,%3}, {%4,%5,%6,%7}, {%8,%9}, {%0,%1,%2,%3};"
                    : "+f"(c[mt][nf][0]), "+f"(c[mt][nf][1]),
                      "+f"(c[mt][nf][2]), "+f"(c[mt][nf][3])
                    : "r"(a[mt][0]), "r"(a[mt][1]), "r"(a[mt][2]), "r"(a[mt][3]),
                      "r"(bf[nf][0]), "r"(bf[nf][1]));
            }
    }
}

__device__ __forceinline__ void frag_writeback(float* out, int ldo, int n0,
                                               int wm, int wn, int lane, float c[2][2][4]) {
    const int g = lane >> 2, tq = lane & 3;
#pragma unroll
    for (int mt = 0; mt < 2; mt++)
#pragma unroll
        for (int nf = 0; nf < 2; nf++) {
            int r = wm + mt * 16 + g;
            int cc = n0 + wn + nf * 8 + tq * 2;
            out[(size_t)r * ldo + cc]           = c[mt][nf][0];
            out[(size_t)r * ldo + cc + 1]       = c[mt][nf][1];
            out[(size_t)(r + 8) * ldo + cc]     = c[mt][nf][2];
            out[(size_t)(r + 8) * ldo + cc + 1] = c[mt][nf][3];
        }
}

__global__ __launch_bounds__(256, 4) void k_loop(
    const float* __restrict__ input_,
    const float* __restrict__ b_ih, const float* __restrict__ b_hh,
    const float* __restrict__ w_cv, const float* __restrict__ w_warp,
    const float* __restrict__ w_ao, const float* __restrict__ b_ao,
    const float* __restrict__ w_pt, const float* __restrict__ b_pt,
    float* __restrict__ out) {
    __shared__ SmemU sm;
    const int bid = blockIdx.x;
    const int tid = threadIdx.x;
    const int lane = tid & 31;
    const int w = tid >> 5;
    const int wm = (w >> 2) * 32;
    const int wn = (w & 3) * 16;

    for (int t = 0; t < T; t++) {
        const int cur = t & 1, nxt = cur ^ 1;
        // ---------- phase A: gates GEMM  [64,2048] = X @ Wr^T, split-K 4x256 ----------
        if (bid < 128) {
            const int nt = bid >> 2, ks = bid & 3;
            const int n0 = nt * 64;
            float c[2][2][4];
#pragma unroll
            for (int i = 0; i < 2; i++)
#pragma unroll
                for (int j = 0; j < 2; j++)
#pragma unroll
                    for (int q = 0; q < 4; q++) c[i][j][q] = 0.f;
            for (int k0 = ks * 256; k0 < ks * 256 + 256; k0 += 64) {
                __syncthreads();
#pragma unroll
                for (int p = 0; p < 2; p++) {
                    int idx = p * 256 + tid;
                    int r = idx >> 3, c8 = (idx & 7) * 8;
                    *(float4*)&sm.gemm.A[r][c8]  = *(const float4*)&g_x_h[(size_t)r * 1024 + k0 + c8];
                    *(float4*)&sm.gemm.Bm[r][c8] = *(const float4*)&g_wr_h[(size_t)(n0 + r) * 1024 + k0 + c8];
                }
                __syncthreads();
                mma_slab(sm.gemm.A, sm.gemm.Bm, wm, wn, lane, c);
            }
            frag_writeback(g_gp4[ks], G4, n0, wm, wn, lane, c);
        }
        gridbar();

        // ---------- phase B: lstm (redundant, c double-buffered) + hde GEMM ----------
        if (bid < 32) {
            const int nt = bid >> 2, ks = bid & 3;
            for (int i = tid; i < 64 * 128; i += 256) {
                int b = i >> 7, jj = i & 127;
                int j = ks * 128 + jj;
                const float* xgp = g_xg + ((size_t)b * T + t) * G4;
                float gi = b_ih[j]           + b_hh[j]           + xgp[j];
                float gf = b_ih[TRG + j]     + b_hh[TRG + j]     + xgp[TRG + j];
                float gg = b_ih[2 * TRG + j] + b_hh[2 * TRG + j] + xgp[2 * TRG + j];
                float go = b_ih[3 * TRG + j] + b_hh[3 * TRG + j] + xgp[3 * TRG + j];
#pragma unroll
                for (int s4 = 0; s4 < 4; s4++) {
                    const float* gp = g_gp4[s4] + b * G4;
                    gi += gp[j]; gf += gp[TRG + j]; gg += gp[2 * TRG + j]; go += gp[3 * TRG + j];
                }
                // read OLD c from cur buffer, write NEW c to nxt buffer (idempotent)
                float cn = sigmoidf_(gf) * g_c[cur][b * TRG + j] + sigmoidf_(gi) * tanhf(gg);
                float hn = sigmoidf_(go) * tanhf(cn);
                g_c[nxt][b * TRG + j] = cn;
                g_h[b * TRG + j] = hn;
                __half h16 = __float2half_rn(hn);
                g_x_h[b * 1024 + 512 + j] = h16;
                sm.hde.A2[jj >> 6][b][jj & 63] = h16;
            }
            __syncthreads();
            const int n0 = nt * 64;
            float c[2][2][4];
#pragma unroll
            for (int i = 0; i < 2; i++)
#pragma unroll
                for (int j = 0; j < 2; j++)
#pragma unroll
                    for (int q = 0; q < 4; q++) c[i][j][q] = 0.f;
#pragma unroll
            for (int slab = 0; slab < 2; slab++) {
                __syncthreads();
                {
                    int rr = tid >> 2;
                    int cc = (tid & 3) * 16;
                    *(float4*)&sm.hde.Bm[rr][cc] =
                        *(const float4*)&g_wde_h[(size_t)(n0 + rr) * TRG + ks * 128 + slab * 64 + cc];
                    *(float4*)&sm.hde.Bm[rr][cc + 8] =
                        *(const float4*)&g_wde_h[(size_t)(n0 + rr) * TRG + ks * 128 + slab * 64 + cc + 8];
                }
                __syncthreads();
                mma_slab(sm.hde.A2[slab], sm.hde.Bm, wm, wn, lane, c);
            }
            frag_writeback(g_hde4[ks], TRG, n0, wm, wn, lane, c);
        }
        gridbar();

        // ---------- phase C: attn logits ----------
        for (int task = bid; task < 1024; task += NBLK) {
            const int b = task >> 4, sb = task & 15;
            __syncthreads();
            for (int i = tid; i < TRG; i += 256) {
                sm.att.hde[i] = g_hde4[0][b * TRG + i] + g_hde4[1][b * TRG + i]
                              + g_hde4[2][b * TRG + i] + g_hde4[3][b * TRG + i];
                sm.att.cv[i]  = w_cv[i];
                sm.att.ww[i]  = w_warp[i];
            }
            __syncthreads();
            const float2* hd2 = (const float2*)sm.att.hde;
            const float2* cv2 = (const float2*)sm.att.cv;
            const float2* ww2 = (const float2*)sm.att.ww;
#pragma unroll
            for (int r = 0; r < 8; r++) {
                const int s = sb * 64 + w * 8 + r;
                const float pa = g_pa[b * S + s];
                const __half2* ep2 = (const __half2*)(g_encproj_h + ((size_t)b * S + s) * TRG);
                float acc = 0.f;
#pragma unroll
                for (int p = 0; p < 8; p++) {
                    int i2 = lane + p * 32;
                    float2 e  = __half22float2(ep2[i2]);
                    float2 hd = hd2[i2], cv = cv2[i2], ww = ww2[i2];
                    acc = fmaf(tanh_ap(e.x + hd.x + pa * cv.x), ww.x, acc);
                    acc = fmaf(tanh_ap(e.y + hd.y + pa * cv.y), ww.y, acc);
                }
                acc = warp_red_sum(acc);
                if (lane == 0) g_attn[b * S + s] = acc;
            }
        }
        gridbar();

        // ---------- phase D: softmax (redundant) + pa + attn out + cenc partial ----------
        if (bid < 256) {
            const int b = bid >> 2, q = bid & 3;
            float4 v4 = *(const float4*)&g_attn[b * S + tid * 4];
            float lm = fmaxf(fmaxf(v4.x, v4.y), fmaxf(v4.z, v4.w));
#pragma unroll
            for (int o = 16; o; o >>= 1) lm = fmaxf(lm, __shfl_xor_sync(0xffffffffu, lm, o));
            if (lane == 0) sm.sm.red[w] = lm;
            __syncthreads();
            float m;
            {
                float mm = sm.sm.red[lane & 7];
#pragma unroll
                for (int o = 4; o; o >>= 1) mm = fmaxf(mm, __shfl_xor_sync(0xffffffffu, mm, o));
                m = mm;
            }
            float ls = __expf(v4.x - m) + __expf(v4.y - m) + __expf(v4.z - m) + __expf(v4.w - m);
            ls = warp_red_sum(ls);
            __syncthreads();
            if (lane == 0) sm.sm.red[w] = ls;
            __syncthreads();
            float sum;
            {
                float ss = sm.sm.red[lane & 7];
#pragma unroll
                for (int o = 4; o; o >>= 1) ss += __shfl_xor_sync(0xffffffffu, ss, o);
                sum = ss;
            }
            const int s = q * 256 + tid;
            float a = __expf(g_attn[b * S + s] - m) / sum;
            sm.sm.satt[tid] = a;
            out[ATTN_OFF + (size_t)t * B * S + (size_t)b * S + s] = a;
            g_pa[b * S + s] += a;
            __syncthreads();
            const __half2* e2 = (const __half2*)g_enc_h + ((size_t)b * S + q * 256) * (ENC / 2) + tid;
            float ax = 0.f, ay = 0.f;
#pragma unroll 4
            for (int ss = 0; ss < 256; ss++) {
                float2 f = __half22float2(e2[(size_t)ss * (ENC / 2)]);
                float wv = sm.sm.satt[ss];
                ax = fmaf(wv, f.x, ax);
                ay = fmaf(wv, f.y, ay);
            }
            g_cenc4[q][b * TRG + tid * 2]     = ax;
            g_cenc4[q][b * TRG + tid * 2 + 1] = ay;
        }
        gridbar();

        // ---------- phase E: ha GEMM + pgen ----------
        if (bid < 128) {
            const int jt = bid >> 3, bt = bid & 7;
            const int j0 = jt * 32, b0 = bt * 8;
            for (int i = tid; i < 8 * 1024; i += 256) {
                int bb = i >> 10, k = i & 1023;
                float v;
                if (k < TRG) {
                    int idx = (b0 + bb) * TRG + k;
                    v = g_cenc4[0][idx] + g_cenc4[1][idx] + g_cenc4[2][idx] + g_cenc4[3][idx];
                } else {
                    v = g_h[(b0 + bb) * TRG + k - TRG];
                }
                sm.ha.X[bb][k] = v;
            }
            __syncthreads();
#pragma unroll
            for (int jj = 0; jj < 4; jj++) {
                const int j = j0 + w * 4 + jj;
                const float* wrow = w_ao + (size_t)j * 1024;
                float acc[8];
#pragma unroll
                for (int bb = 0; bb < 8; bb++) acc[bb] = 0.f;
#pragma unroll
                for (int i = 0; i < 8; i++) {
                    int k = i * 128 + lane * 4;
                    float4 wv = *(const float4*)&wrow[k];
#pragma unroll
                    for (int bb = 0; bb < 8; bb++) {
                        float4 xv = *(const float4*)&sm.ha.X[bb][k];
                        acc[bb] += wv.x * xv.x + wv.y * xv.y + wv.z * xv.z + wv.w * xv.w;
                    }
                }
#pragma unroll
                for (int bb = 0; bb < 8; bb++) {
                    float r = warp_red_sum(acc[bb]);
                    if (lane == 0) {
                        r += b_ao[j];
                        int b = b0 + bb;
                        g_ha[b * TRG + j] = r;
                        g_x_h[b * 1024 + j] = __float2half_rn(r);
                        out[OUT_OFF + ((size_t)b * T + t) * TRG + j] = r;
                    }
                }
            }
            __syncthreads();
        } else if (bid == 128) {
#pragma unroll
            for (int r = 0; r < 8; r++) {
                int b = w * 8 + r;
                const float* xt = input_ + ((size_t)b * T + t) * IN;
                float acc = 0.f;
                for (int k = lane; k < IN; k += 32)  acc = fmaf(w_pt[k], xt[k], acc);
                for (int k = lane; k < TRG; k += 32) acc = fmaf(w_pt[IN + k], g_h[b * TRG + k], acc);
                for (int k = lane; k < TRG; k += 32) {
                    int idx = b * TRG + k;
                    float cv = g_cenc4[0][idx] + g_cenc4[1][idx] + g_cenc4[2][idx] + g_cenc4[3][idx];
                    acc = fmaf(w_pt[IN + TRG + k], cv, acc);
                }
                acc = warp_red_sum(acc);
                if (lane == 0) out[PGEN_OFF + (size_t)b * T + t] = sigmoidf_(acc + b_pt[0]);
            }
        }
        gridbar();
    }
}

// ---------------- finalize ----------------
__global__ void k_final(float* __restrict__ out, const float* __restrict__ past_dehy) {
    int i = blockIdx.x * blockDim.x + threadIdx.x;
    if (i < B * TRG) {
        out[HT_OFF + i]  = g_h[i];
        out[CT_OFF + i]  = g_c[0][i];   // T=100 even -> final c lands in buffer 0
        out[HAT_OFF + i] = g_ha[i];
        out[PDH_OFF + i] = past_dehy[i];
    }
    if (i < B * S) out[PAT_OFF + i] = g_pa[i];
    if (i == 0) out[LOSS_OFF] = 0.f;
}

// ---------------- launch ----------------
extern "C" void kernel_launch(void* const* d_in, const int* in_sizes, int n_in,
                              void* d_out, int out_size) {
    const float* input_    = (const float*)d_in[1];
    const float* h0        = (const float*)d_in[2];
    const float* c0        = (const float*)d_in[3];
    const float* h_attn    = (const float*)d_in[4];
    const float* enc       = (const float*)d_in[5];
    const float* past_attn = (const float*)d_in[6];
    const float* past_dehy = (const float*)d_in[7];
    const float* w_ih      = (const float*)d_in[8];
    const float* b_ih      = (const float*)d_in[9];
    const float* w_hh      = (const float*)d_in[10];
    const float* b_hh      = (const float*)d_in[11];
    const float* w_en      = (const float*)d_in[12];
    const float* b_en      = (const float*)d_in[13];
    const float* w_de      = (const float*)d_in[14];
    const float* w_cv      = (const float*)d_in[15];
    const float* w_warp    = (const float*)d_in[16];
    const float* w_ao      = (const float*)d_in[17];
    const float* b_ao      = (const float*)d_in[18];
    const float* w_pt      = (const float*)d_in[19];
    const float* b_pt      = (const float*)d_in[20];
    float* out = (float*)d_out;

    __half *p_enc_h, *p_wen_h, *p_input_h, *p_encproj_h, *p_wihx_h;
    float *p_xg;
    cudaGetSymbolAddress((void**)&p_enc_h, g_enc_h);
    cudaGetSymbolAddress((void**)&p_wen_h, g_wen_h);
    cudaGetSymbolAddress((void**)&p_input_h, g_input_h);
    cudaGetSymbolAddress((void**)&p_encproj_h, g_encproj_h);
    cudaGetSymbolAddress((void**)&p_wihx_h, g_wihx_h);
    cudaGetSymbolAddress((void**)&p_xg, g_xg);

    {
        __half* p_wde_h;
        cudaGetSymbolAddress((void**)&p_wde_h, g_wde_h);
        k_init<<<(B * S + 255) / 256, 256>>>(h0, c0, h_attn, past_attn);
        k_f2h<<<(B * S * ENC) / 1024, 256>>>(enc, p_enc_h);
        k_f2h<<<(512 * 512) / 1024, 256>>>(w_en, p_wen_h);
        k_f2h<<<(B * T * IN) / 1024, 256>>>(input_, p_input_h);
        k_f2h<<<(TRG * TRG) / 1024, 256>>>(w_de, p_wde_h);
        k_wihx<<<G4, 64>>>(w_ih);
        k_wr<<<G4, 256>>>(w_ih, w_hh);
    }

    k_mma<true><<<dim3(512 / 64, (B * S) / 128), 256>>>(p_enc_h, p_wen_h, b_en,
                                                        p_encproj_h, 512, 512);
    k_mma<false><<<dim3(G4 / 64, (B * T) / 128), 256>>>(p_input_h, p_wihx_h, nullptr,
                                                        p_xg, IN, G4);

    k_loop<<<NBLK, 256>>>(input_, b_ih, b_hh, w_cv, w_warp, w_ao, b_ao, w_pt, b_pt, out);

    k_final<<<(B * S + 255) / 256, 256>>>(out, past_dehy);
}

// round 9
// speedup vs baseline: 1.4097x; 1.4097x over previous
#include <cuda_runtime.h>
#include <cuda_fp16.h>
#include <math.h>

// Problem constants
#define B   64
#define T   100
#define S   1024
#define IN  256
#define TRG 512
#define ENC 512
#define G4  2048   // 4*TRG

// Output layout offsets (floats)
#define OUT_OFF   0
#define HT_OFF    3276800
#define CT_OFF    3309568
#define HAT_OFF   3342336
#define ATTN_OFF  3375104
#define PAT_OFF   9928704
#define PGEN_OFF  9994240
#define PDH_OFF   10000640
#define LOSS_OFF  10033408

// ---------------- device state ----------------
__device__ __align__(16) __half  g_encproj_h[(size_t)B * S * TRG];   // 67 MB
__device__ __align__(16) __half  g_enc_h[(size_t)B * S * ENC];       // 67 MB
__device__ __align__(16) __half  g_wen_h[512 * 512];
__device__ __align__(16) __half  g_input_h[B * T * IN];
__device__ __align__(16) __half  g_wihx_h[G4 * IN];
__device__ __align__(16) __half  g_wr_h[(size_t)G4 * 1024];
__device__ __align__(16) __half  g_wde_h[TRG * TRG];
__device__ __align__(16) __half  g_x_h[B * 1024];                    // [ha | h] fp16
__device__ __align__(16) float   g_xg[(size_t)B * T * G4];
__device__ __align__(16) float g_h[B * TRG];
__device__ __align__(16) float g_c[2][B * TRG];                      // double-buffered
__device__ __align__(16) float g_ha[B * TRG];
__device__ __align__(16) float g_pa[B * S];
__device__ __align__(16) float g_gp4[4][B * G4];
__device__ __align__(16) float g_hde4[4][B * TRG];
__device__ __align__(16) float g_attn[B * S];                        // unnormalized exps
__device__ __align__(16) float g_pm[B * 16];                         // chunk max
__device__ __align__(16) float g_ps[B * 16];                         // chunk expsum
__device__ __align__(16) float g_cencP[16][B * TRG];                 // cenc chunk partials
__device__ __align__(16) float g_cenc[B * TRG];

__device__ __forceinline__ float warp_red_sum(float v) {
#pragma unroll
    for (int o = 16; o; o >>= 1) v += __shfl_xor_sync(0xffffffffu, v, o);
    return v;
}
__device__ __forceinline__ float sigmoidf_(float x) { return 1.0f / (1.0f + expf(-x)); }
__device__ __forceinline__ float tanh_ap(float x) {
    float y; asm("tanh.approx.f32 %0, %1;" : "=f"(y) : "f"(x)); return y;
}
__device__ __forceinline__ unsigned smem_u32(const void* p) {
    return (unsigned)__cvta_generic_to_shared(p);
}

// ---------------- init ----------------
__global__ void k_init(const float* __restrict__ h0, const float* __restrict__ c0,
                       const float* __restrict__ h_attn, const float* __restrict__ past_attn) {
    int i = blockIdx.x * blockDim.x + threadIdx.x;
    if (i < B * TRG) {
        g_h[i] = h0[i]; g_c[0][i] = c0[i]; g_ha[i] = h_attn[i];
        int b = i >> 9, j = i & 511;
        g_x_h[b * 1024 + j]       = __float2half_rn(h_attn[i]);
        g_x_h[b * 1024 + 512 + j] = __float2half_rn(h0[i]);
    }
    if (i < B * S) g_pa[i] = past_attn[i];
}

__global__ void k_f2h(const float* __restrict__ src, __half* __restrict__ dst) {
    size_t i = ((size_t)blockIdx.x * blockDim.x + threadIdx.x) * 4;
    float4 v = *(const float4*)&src[i];
    __half2* d = (__half2*)&dst[i];
    d[0] = __floats2half2_rn(v.x, v.y);
    d[1] = __floats2half2_rn(v.z, v.w);
}

__global__ void k_wihx(const float* __restrict__ w_ih) {
    int n = blockIdx.x;
    for (int c = threadIdx.x; c < IN; c += 64)
        g_wihx_h[n * IN + c] = __float2half_rn(w_ih[(size_t)n * (IN + TRG) + c]);
}

__global__ void k_wr(const float* __restrict__ w_ih, const float* __restrict__ w_hh) {
    int n = blockIdx.x;
    for (int k = threadIdx.x; k < 1024; k += 256) {
        float v = (k < TRG) ? w_ih[(size_t)n * (IN + TRG) + IN + k]
                            : w_hh[(size_t)n * TRG + k - TRG];
        g_wr_h[(size_t)n * 1024 + k] = __float2half_rn(v);
    }
}

// ---------------- setup fp16 TC GEMM (encproj, xg) ----------------
template<bool OUT16>
__global__ void k_mma(const __half* __restrict__ A, const __half* __restrict__ W,
                      const float* __restrict__ bias, void* __restrict__ Cout,
                      int K, int ldc) {
    __shared__ __align__(16) char smem_raw[128 * 68 * 4];
    __shared__ float sBias[64];
    __half (*sA)[72] = (__half(*)[72])smem_raw;
    __half (*sB)[72] = (__half(*)[72])(smem_raw + 18432);

    const int m0 = blockIdx.y * 128;
    const int n0 = blockIdx.x * 64;
    const int tid = threadIdx.x;
    const int lane = tid & 31;
    const int w = tid >> 5;
    const int wm = (w >> 1) * 32;
    const int wn = (w & 1) * 32;

    if (OUT16 && tid < 64) sBias[tid] = bias[n0 + tid];

    float c[2][4][4];
#pragma unroll
    for (int i = 0; i < 2; i++)
#pragma unroll
        for (int j = 0; j < 4; j++)
#pragma unroll
            for (int q = 0; q < 4; q++) c[i][j][q] = 0.f;

    const int lrow = lane & 15;
    const int lcol = (lane >> 4) * 8;

    for (int k0 = 0; k0 < K; k0 += 64) {
        __syncthreads();
        {
            int r = tid >> 3, cc = (tid & 7) * 8;
#pragma unroll
            for (int p = 0; p < 4; p++)
                *(float4*)&sA[r + p * 32][cc] =
                    *(const float4*)&A[(size_t)(m0 + r + p * 32) * K + k0 + cc];
#pragma unroll
            for (int p = 0; p < 2; p++)
                *(float4*)&sB[r + p * 32][cc] =
                    *(const float4*)&W[(size_t)(n0 + r + p * 32) * K + k0 + cc];
        }
        __syncthreads();
#pragma unroll
        for (int kk = 0; kk < 4; kk++) {
            unsigned a[2][4], bf[4][2];
#pragma unroll
            for (int mt = 0; mt < 2; mt++) {
                unsigned addr = smem_u32(&sA[wm + mt * 16 + lrow][kk * 16 + lcol]);
                asm volatile("ldmatrix.sync.aligned.m8n8.x4.shared.b16 {%0,%1,%2,%3}, [%4];"
                             : "=r"(a[mt][0]), "=r"(a[mt][1]), "=r"(a[mt][2]), "=r"(a[mt][3])
                             : "r"(addr));
            }
#pragma unroll
            for (int bp = 0; bp < 2; bp++) {
                unsigned r0, r1, r2, r3;
                unsigned addr = smem_u32(&sB[wn + bp * 16 + lrow][kk * 16 + lcol]);
                asm volatile("ldmatrix.sync.aligned.m8n8.x4.shared.b16 {%0,%1,%2,%3}, [%4];"
                             : "=r"(r0), "=r"(r1), "=r"(r2), "=r"(r3) : "r"(addr));
                bf[bp * 2 + 0][0] = r0; bf[bp * 2 + 0][1] = r2;
                bf[bp * 2 + 1][0] = r1; bf[bp * 2 + 1][1] = r3;
            }
#pragma unroll
            for (int mt = 0; mt < 2; mt++)
#pragma unroll
                for (int nf = 0; nf < 4; nf++) {
                    asm volatile(
                        "mma.sync.aligned.m16n8k16.row.col.f32.f16.f16.f32 "
                        "{%0,%1,%2,%3}, {%4,%5,%6,%7}, {%8,%9}, {%0,%1,%2,%3};"
                        : "+f"(c[mt][nf][0]), "+f"(c[mt][nf][1]),
                          "+f"(c[mt][nf][2]), "+f"(c[mt][nf][3])
                        : "r"(a[mt][0]), "r"(a[mt][1]), "r"(a[mt][2]), "r"(a[mt][3]),
                          "r"(bf[nf][0]), "r"(bf[nf][1]));
                }
        }
    }
    __syncthreads();
    float (*sO)[68] = (float(*)[68])smem_raw;
    {
        int g = lane >> 2, tq = lane & 3;
#pragma unroll
        for (int mt = 0; mt < 2; mt++)
#pragma unroll
            for (int nf = 0; nf < 4; nf++) {
                int r = wm + mt * 16 + g;
                int cc = wn + (nf >> 1) * 16 + (nf & 1) * 8 + tq * 2;
                sO[r][cc]     = c[mt][nf][0]; sO[r][cc + 1]     = c[mt][nf][1];
                sO[r + 8][cc] = c[mt][nf][2]; sO[r + 8][cc + 1] = c[mt][nf][3];
            }
    }
    __syncthreads();
#pragma unroll
    for (int p = 0; p < 4; p++) {
        int idx = p * 256 + tid;
        int r = idx >> 3, c8 = (idx & 7) * 8;
        if (OUT16) {
            __half* C = (__half*)Cout;
            __half2 h[4];
#pragma unroll
            for (int q = 0; q < 4; q++)
                h[q] = __floats2half2_rn(sO[r][c8 + 2 * q] + sBias[c8 + 2 * q],
                                         sO[r][c8 + 2 * q + 1] + sBias[c8 + 2 * q + 1]);
            *(float4*)&C[(size_t)(m0 + r) * ldc + n0 + c8] = *(float4*)h;
        } else {
            float* C = (float*)Cout;
            *(float4*)&C[(size_t)(m0 + r) * ldc + n0 + c8]     = *(float4*)&sO[r][c8];
            *(float4*)&C[(size_t)(m0 + r) * ldc + n0 + c8 + 4] = *(float4*)&sO[r][c8 + 4];
        }
    }
}

// ---------------- shared mma helpers ----------------
__device__ __forceinline__ void mma_slab(const __half (*sA)[72], const __half (*sB)[72],
                                         int wm, int wn, int lane, float c[2][2][4]) {
    const int lrow = lane & 15;
    const int lcol = (lane >> 4) * 8;
#pragma unroll
    for (int kk = 0; kk < 4; kk++) {
        unsigned a[2][4], bf[2][2];
#pragma unroll
        for (int mt = 0; mt < 2; mt++) {
            unsigned addr = smem_u32(&sA[wm + mt * 16 + lrow][kk * 16 + lcol]);
            asm volatile("ldmatrix.sync.aligned.m8n8.x4.shared.b16 {%0,%1,%2,%3}, [%4];"
                         : "=r"(a[mt][0]), "=r"(a[mt][1]), "=r"(a[mt][2]), "=r"(a[mt][3])
                         : "r"(addr));
        }
        {
            unsigned r0, r1, r2, r3;
            unsigned addr = smem_u32(&sB[wn + lrow][kk * 16 + lcol]);
            asm volatile("ldmatrix.sync.aligned.m8n8.x4.shared.b16 {%0,%1,%2,%3}, [%4];"
                         : "=r"(r0), "=r"(r1), "=r"(r2), "=r"(r3) : "r"(addr));
            bf[0][0] = r0; bf[0][1] = r2;
            bf[1][0] = r1; bf[1][1] = r3;
        }
#pragma unroll
        for (int mt = 0; mt < 2; mt++)
#pragma unroll
            for (int nf = 0; nf < 2; nf++) {
                asm volatile(
                    "mma.sync.aligned.m16n8k16.row.col.f32.f16.f16.f32 "
                    "{%0,%1,%2,%3}, {%4,%5,%6,%7}, {%8,%9}, {%0,%1,%2,%3};"
                    : "+f"(c[mt][nf][0]), "+f"(c[mt][nf][1]),
                      "+f"(c[mt][nf][2]), "+f"(c[mt][nf][3])
                    : "r"(a[mt][0]), "r"(a[mt][1]), "r"(a[mt][2]), "r"(a[mt][3]),
                      "r"(bf[nf][0]), "r"(bf[nf][1]));
            }
    }
}

__device__ __forceinline__ void frag_writeback(float* out, int ldo, int n0,
                                               int wm, int wn, int lane, float c[2][2][4]) {
    const int g = lane >> 2, tq = lane & 3;
#pragma unroll
    for (int mt = 0; mt < 2; mt++)
#pragma unroll
        for (int nf = 0; nf < 2; nf++) {
            int r = wm + mt * 16 + g;
            int cc = n0 + wn + nf * 8 + tq * 2;
            out[(size_t)r * ldo + cc]           = c[mt][nf][0];
            out[(size_t)r * ldo + cc + 1]       = c[mt][nf][1];
            out[(size_t)(r + 8) * ldo + cc]     = c[mt][nf][2];
            out[(size_t)(r + 8) * ldo + cc + 1] = c[mt][nf][3];
        }
}

// ---------------- per-step TC GEMM (gates): M=64, split-K ----------------
__global__ void k_tc_gemm(const __half* __restrict__ A, int lda,
                          const __half* __restrict__ W, int ldw,
                          float* __restrict__ outP, int ldo, int kps) {
    __shared__ __align__(16) __half sA[64][72];
    __shared__ __align__(16) __half sB[64][72];
    const int n0 = blockIdx.x * 64;
    const int kbase = blockIdx.y * kps;
    float* out = outP + (size_t)blockIdx.y * 64 * ldo;
    const int tid = threadIdx.x;
    const int lane = tid & 31;
    const int w = tid >> 5;
    const int wm = (w >> 2) * 32;
    const int wn = (w & 3) * 16;

    float c[2][2][4];
#pragma unroll
    for (int i = 0; i < 2; i++)
#pragma unroll
        for (int j = 0; j < 2; j++)
#pragma unroll
            for (int q = 0; q < 4; q++) c[i][j][q] = 0.f;

    for (int k0 = kbase; k0 < kbase + kps; k0 += 64) {
        __syncthreads();
#pragma unroll
        for (int p = 0; p < 2; p++) {
            int idx = p * 256 + tid;
            int r = idx >> 3, c8 = (idx & 7) * 8;
            *(float4*)&sA[r][c8] = *(const float4*)&A[(size_t)r * lda + k0 + c8];
            *(float4*)&sB[r][c8] = *(const float4*)&W[(size_t)(n0 + r) * ldw + k0 + c8];
        }
        __syncthreads();
        mma_slab(sA, sB, wm, wn, lane, c);
    }
    frag_writeback(out, ldo, n0, wm, wn, lane, c);
}

// ---------------- K2: lstm (redundant, c double-buffered) + hde TC GEMM ----------------
// grid 32: nt = bid>>2 (hde n-tile), ks = bid&3 (lstm j-chunk & hde k-split)
__global__ void k_lstm_hde(const float* __restrict__ b_ih, const float* __restrict__ b_hh,
                           int cur, int t) {
    __shared__ __align__(16) __half A2[2][64][72];
    __shared__ __align__(16) __half Bm[64][72];
    const int bid = blockIdx.x;
    const int nt = bid >> 2, ks = bid & 3;
    const int tid = threadIdx.x;
    const int lane = tid & 31, w = tid >> 5;
    const int wm = (w >> 2) * 32, wn = (w & 3) * 16;
    const int nxt = cur ^ 1;

    for (int i = tid; i < 64 * 128; i += 256) {
        int b = i >> 7, jj = i & 127;
        int j = ks * 128 + jj;
        const float* xgp = g_xg + ((size_t)b * T + t) * G4;
        float gi = b_ih[j]           + b_hh[j]           + xgp[j];
        float gf = b_ih[TRG + j]     + b_hh[TRG + j]     + xgp[TRG + j];
        float gg = b_ih[2 * TRG + j] + b_hh[2 * TRG + j] + xgp[2 * TRG + j];
        float go = b_ih[3 * TRG + j] + b_hh[3 * TRG + j] + xgp[3 * TRG + j];
#pragma unroll
        for (int s4 = 0; s4 < 4; s4++) {
            const float* gp = g_gp4[s4] + b * G4;
            gi += gp[j]; gf += gp[TRG + j]; gg += gp[2 * TRG + j]; go += gp[3 * TRG + j];
        }
        float cn = sigmoidf_(gf) * g_c[cur][b * TRG + j] + sigmoidf_(gi) * tanhf(gg);
        float hn = sigmoidf_(go) * tanhf(cn);
        g_c[nxt][b * TRG + j] = cn;
        g_h[b * TRG + j] = hn;
        __half h16 = __float2half_rn(hn);
        g_x_h[b * 1024 + 512 + j] = h16;
        A2[jj >> 6][b][jj & 63] = h16;
    }
    __syncthreads();
    const int n0 = nt * 64;
    float c[2][2][4];
#pragma unroll
    for (int i = 0; i < 2; i++)
#pragma unroll
        for (int j = 0; j < 2; j++)
#pragma unroll
            for (int q = 0; q < 4; q++) c[i][j][q] = 0.f;
#pragma unroll
    for (int slab = 0; slab < 2; slab++) {
        __syncthreads();
        {
            int rr = tid >> 2;
            int cc = (tid & 3) * 16;
            *(float4*)&Bm[rr][cc] =
                *(const float4*)&g_wde_h[(size_t)(n0 + rr) * TRG + ks * 128 + slab * 64 + cc];
            *(float4*)&Bm[rr][cc + 8] =
                *(const float4*)&g_wde_h[(size_t)(n0 + rr) * TRG + ks * 128 + slab * 64 + cc + 8];
        }
        __syncthreads();
        mma_slab(A2[slab], Bm, wm, wn, lane, c);
    }
    frag_writeback(g_hde4[ks], TRG, n0, wm, wn, lane, c);
}

// ---------------- K3: flash attn — logits + local softmax + cenc partial ----------------
// grid (16, 64), block 256. Block = (s-chunk sb, batch b), 64 s per chunk.
__global__ void k_attn_flash(const float* __restrict__ w_cv, const float* __restrict__ w_warp) {
    __shared__ __align__(16) float sh_hde[TRG], sh_cv[TRG], sh_w[TRG];
    __shared__ float sl[64], se[64];
    const int sb = blockIdx.x, b = blockIdx.y;
    const int tid = threadIdx.x, lane = tid & 31, w = tid >> 5;

    for (int i = tid; i < TRG; i += 256) {
        sh_hde[i] = g_hde4[0][b * TRG + i] + g_hde4[1][b * TRG + i]
                  + g_hde4[2][b * TRG + i] + g_hde4[3][b * TRG + i];
        sh_cv[i]  = w_cv[i];
        sh_w[i]   = w_warp[i];
    }
    __syncthreads();
    const float2* hd2 = (const float2*)sh_hde;
    const float2* cv2 = (const float2*)sh_cv;
    const float2* ww2 = (const float2*)sh_w;
#pragma unroll
    for (int r = 0; r < 8; r++) {
        const int s = sb * 64 + w * 8 + r;
        const float pa = g_pa[b * S + s];
        const __half2* ep2 = (const __half2*)(g_encproj_h + ((size_t)b * S + s) * TRG);
        float acc = 0.f;
#pragma unroll
        for (int p = 0; p < 8; p++) {
            int i2 = lane + p * 32;
            float2 e  = __half22float2(ep2[i2]);
            float2 hd = hd2[i2], cv = cv2[i2], ww = ww2[i2];
            acc = fmaf(tanh_ap(e.x + hd.x + pa * cv.x), ww.x, acc);
            acc = fmaf(tanh_ap(e.y + hd.y + pa * cv.y), ww.y, acc);
        }
        acc = warp_red_sum(acc);
        if (lane == 0) sl[w * 8 + r] = acc;
    }
    __syncthreads();
    // local max (broadcast loop, deterministic)
    float m = sl[0];
#pragma unroll
    for (int i = 1; i < 64; i++) m = fmaxf(m, sl[i]);
    if (tid < 64) se[tid] = __expf(sl[tid] - m);
    __syncthreads();
    if (tid < 64) g_attn[b * S + sb * 64 + tid] = se[tid];
    if (tid == 0) {
        float sum = 0.f;
#pragma unroll
        for (int i = 0; i < 64; i++) sum += se[i];
        g_pm[b * 16 + sb] = m;
        g_ps[b * 16 + sb] = sum;
    }
    // cenc partial (unnormalized): thread = half2 e-col
    const __half2* e2 = (const __half2*)g_enc_h + ((size_t)b * S + sb * 64) * (ENC / 2) + tid;
    float ax = 0.f, ay = 0.f;
#pragma unroll 4
    for (int s = 0; s < 64; s++) {
        float2 f = __half22float2(e2[(size_t)s * (ENC / 2)]);
        float wv = se[s];
        ax = fmaf(wv, f.x, ax);
        ay = fmaf(wv, f.y, ay);
    }
    g_cencP[sb][b * TRG + tid * 2]     = ax;
    g_cencP[sb][b * TRG + tid * 2 + 1] = ay;
}

// ---------------- K4: combine chunks -> attn out, pa, cenc ----------------
// grid 64 (b), block 1024
__global__ void k_attn_fin(float* __restrict__ out_attn_t) {
    __shared__ float m16[16], s16[16];
    const int b = blockIdx.x, tid = threadIdx.x;
    if (tid < 16) { m16[tid] = g_pm[b * 16 + tid]; s16[tid] = g_ps[b * 16 + tid]; }
    __syncthreads();
    float m = m16[0];
#pragma unroll
    for (int i = 1; i < 16; i++) m = fmaxf(m, m16[i]);
    float tot = 0.f;
#pragma unroll
    for (int i = 0; i < 16; i++) tot += s16[i] * __expf(m16[i] - m);
    const float inv = 1.0f / tot;
    const int sb = tid >> 6;
    float a = g_attn[b * S + tid] * (__expf(m16[sb] - m) * inv);
    out_attn_t[(size_t)b * S + tid] = a;
    g_pa[b * S + tid] += a;
    if (tid < TRG) {
        float acc = 0.f;
#pragma unroll
        for (int q = 0; q < 16; q++)
            acc = fmaf(g_cencP[q][b * TRG + tid], __expf(m16[q] - m), acc);
        g_cenc[b * TRG + tid] = acc * inv;
    }
}

// ---------------- K5: ha GEMM + pgen ----------------
// grid 129: blocks 0..127 = (jt,bt); block 128 = pgen
__global__ void k_ha_pgen(const float* __restrict__ w_ao, const float* __restrict__ b_ao,
                          const float* __restrict__ input_, const float* __restrict__ w_pt,
                          const float* __restrict__ b_pt, float* __restrict__ out, int t) {
    __shared__ __align__(16) float sX[8][1024];
    const int tid = threadIdx.x;
    if (blockIdx.x < 128) {
        const int jt = blockIdx.x >> 3, bt = blockIdx.x & 7;
        const int j0 = jt * 32, b0 = bt * 8;
        for (int i = tid; i < 8 * 1024; i += 256) {
            int bb = i >> 10, k = i & 1023;
            sX[bb][k] = (k < TRG) ? g_cenc[(b0 + bb) * TRG + k]
                                  : g_h[(b0 + bb) * TRG + k - TRG];
        }
        __syncthreads();
        const int warp = tid >> 5, lane = tid & 31;
#pragma unroll
        for (int jj = 0; jj < 4; jj++) {
            const int j = j0 + warp * 4 + jj;
            const float* wrow = w_ao + (size_t)j * 1024;
            float acc[8];
#pragma unroll
            for (int bb = 0; bb < 8; bb++) acc[bb] = 0.f;
#pragma unroll
            for (int i = 0; i < 8; i++) {
                int k = i * 128 + lane * 4;
                float4 wv = *(const float4*)&wrow[k];
#pragma unroll
                for (int bb = 0; bb < 8; bb++) {
                    float4 xv = *(const float4*)&sX[bb][k];
                    acc[bb] += wv.x * xv.x + wv.y * xv.y + wv.z * xv.z + wv.w * xv.w;
                }
            }
#pragma unroll
            for (int bb = 0; bb < 8; bb++) {
                float r = warp_red_sum(acc[bb]);
                if (lane == 0) {
                    r += b_ao[j];
                    int b = b0 + bb;
                    g_ha[b * TRG + j] = r;
                    g_x_h[b * 1024 + j] = __float2half_rn(r);
                    out[OUT_OFF + ((size_t)b * T + t) * TRG + j] = r;
                }
            }
        }
    } else {
        const int warp = tid >> 5, lane = tid & 31;
#pragma unroll
        for (int r = 0; r < 8; r++) {
            int b = warp * 8 + r;
            const float* xt = input_ + ((size_t)b * T + t) * IN;
            float acc = 0.f;
            for (int k = lane; k < IN; k += 32)  acc = fmaf(w_pt[k], xt[k], acc);
            for (int k = lane; k < TRG; k += 32) acc = fmaf(w_pt[IN + k], g_h[b * TRG + k], acc);
            for (int k = lane; k < TRG; k += 32) acc = fmaf(w_pt[IN + TRG + k], g_cenc[b * TRG + k], acc);
            acc = warp_red_sum(acc);
            if (lane == 0) out[PGEN_OFF + (size_t)b * T + t] = sigmoidf_(acc + b_pt[0]);
        }
    }
}

// ---------------- finalize ----------------
__global__ void k_final(float* __restrict__ out, const float* __restrict__ past_dehy) {
    int i = blockIdx.x * blockDim.x + threadIdx.x;
    if (i < B * TRG) {
        out[HT_OFF + i]  = g_h[i];
        out[CT_OFF + i]  = g_c[0][i];   // T even -> final c in buffer 0
        out[HAT_OFF + i] = g_ha[i];
        out[PDH_OFF + i] = past_dehy[i];
    }
    if (i < B * S) out[PAT_OFF + i] = g_pa[i];
    if (i == 0) out[LOSS_OFF] = 0.f;
}

// ---------------- launch ----------------
extern "C" void kernel_launch(void* const* d_in, const int* in_sizes, int n_in,
                              void* d_out, int out_size) {
    const float* input_    = (const float*)d_in[1];
    const float* h0        = (const float*)d_in[2];
    const float* c0        = (const float*)d_in[3];
    const float* h_attn    = (const float*)d_in[4];
    const float* enc       = (const float*)d_in[5];
    const float* past_attn = (const float*)d_in[6];
    const float* past_dehy = (const float*)d_in[7];
    const float* w_ih      = (const float*)d_in[8];
    const float* b_ih      = (const float*)d_in[9];
    const float* w_hh      = (const float*)d_in[10];
    const float* b_hh      = (const float*)d_in[11];
    const float* w_en      = (const float*)d_in[12];
    const float* b_en      = (const float*)d_in[13];
    const float* w_de      = (const float*)d_in[14];
    const float* w_cv      = (const float*)d_in[15];
    const float* w_warp    = (const float*)d_in[16];
    const float* w_ao      = (const float*)d_in[17];
    const float* b_ao      = (const float*)d_in[18];
    const float* w_pt      = (const float*)d_in[19];
    const float* b_pt      = (const float*)d_in[20];
    float* out = (float*)d_out;

    __half *p_enc_h, *p_wen_h, *p_input_h, *p_encproj_h, *p_wihx_h, *p_wr_h, *p_wde_h, *p_x_h;
    float *p_xg, *p_gp4;
    cudaGetSymbolAddress((void**)&p_enc_h, g_enc_h);
    cudaGetSymbolAddress((void**)&p_wen_h, g_wen_h);
    cudaGetSymbolAddress((void**)&p_input_h, g_input_h);
    cudaGetSymbolAddress((void**)&p_encproj_h, g_encproj_h);
    cudaGetSymbolAddress((void**)&p_wihx_h, g_wihx_h);
    cudaGetSymbolAddress((void**)&p_wr_h, g_wr_h);
    cudaGetSymbolAddress((void**)&p_wde_h, g_wde_h);
    cudaGetSymbolAddress((void**)&p_x_h, g_x_h);
    cudaGetSymbolAddress((void**)&p_xg, g_xg);
    cudaGetSymbolAddress((void**)&p_gp4, g_gp4);

    k_init<<<(B * S + 255) / 256, 256>>>(h0, c0, h_attn, past_attn);
    k_f2h<<<(B * S * ENC) / 1024, 256>>>(enc, p_enc_h);
    k_f2h<<<(512 * 512) / 1024, 256>>>(w_en, p_wen_h);
    k_f2h<<<(B * T * IN) / 1024, 256>>>(input_, p_input_h);
    k_f2h<<<(TRG * TRG) / 1024, 256>>>(w_de, p_wde_h);
    k_wihx<<<G4, 64>>>(w_ih);
    k_wr<<<G4, 256>>>(w_ih, w_hh);

    k_mma<true><<<dim3(512 / 64, (B * S) / 128), 256>>>(p_enc_h, p_wen_h, b_en,
                                                        p_encproj_h, 512, 512);
    k_mma<false><<<dim3(G4 / 64, (B * T) / 128), 256>>>(p_input_h, p_wihx_h, nullptr,
                                                        p_xg, IN, G4);

    for (int t = 0; t < T; t++) {
        int cur = t & 1;
        k_tc_gemm<<<dim3(32, 4), 256>>>(p_x_h, 1024, p_wr_h, 1024, p_gp4, G4, 256);
        k_lstm_hde<<<32, 256>>>(b_ih, b_hh, cur, t);
        k_attn_flash<<<dim3(16, B), 256>>>(w_cv, w_warp);
        k_attn_fin<<<B, 1024>>>(out + ATTN_OFF + (size_t)t * B * S);
        k_ha_pgen<<<129, 256>>>(w_ao, b_ao, input_, w_pt, b_pt, out, t);
    }
    k_final<<<(B * S + 255) / 256, 256>>>(out, past_dehy);
}